// round 16
// baseline (speedup 1.0000x reference)
#include <cuda_runtime.h>
#include <cstdint>

#define BATCH    64
#define SEQ      8192
#define RDIM     80
#define NSLOT    264           // 256-slot ring + 8 mirror slots (dup of 0..7)
#define CHUNK    8
#define NX       320           // producer threads (warps 0-9)
#define NE       160           // epilogue threads (warps 10-14)
#define NTHREADS (NX + NE)     // 480

typedef unsigned long long u64;

__device__ __forceinline__ u64 ffma2(u64 a, u64 b, u64 c) {
    u64 d;
    asm("fma.rn.f32x2 %0, %1, %2, %3;" : "=l"(d) : "l"(a), "l"(b), "l"(c));
    return d;
}
__device__ __forceinline__ u64 fadd2(u64 a, u64 b) {
    u64 d;
    asm("add.rn.f32x2 %0, %1, %2;" : "=l"(d) : "l"(a), "l"(b));
    return d;
}
__device__ __forceinline__ float2 unpack2(u64 v) {
    unsigned lo, hi;
    asm("mov.b64 {%0, %1}, %2;" : "=r"(lo), "=r"(hi) : "l"(v));
    float2 r; r.x = __uint_as_float(lo); r.y = __uint_as_float(hi);
    return r;
}
__device__ __forceinline__ float fast_tanh(float v) {
    v = fminf(fmaxf(v, -15.0f), 15.0f);
    float u = __expf(-2.0f * v);
    return __fdividef(1.0f - u, 1.0f + u);
}

// Barrier A (id 1): epilogue arrives (h[t] published), producers sync.
// Barrier B (id 2): producers arrive (partials published), epilogue syncs.
// Barrier E (id 3): epilogue-internal sync (h[t-1] visible within group).
#define BAR_SYNC_A()   asm volatile("bar.sync 1, %0;"   :: "n"(NTHREADS) : "memory")
#define BAR_ARRIVE_A() asm volatile("bar.arrive 1, %0;" :: "n"(NTHREADS) : "memory")
#define BAR_SYNC_B()   asm volatile("bar.sync 2, %0;"   :: "n"(NTHREADS) : "memory")
#define BAR_ARRIVE_B() asm volatile("bar.arrive 2, %0;" :: "n"(NTHREADS) : "memory")
#define BAR_SYNC_E()   asm volatile("bar.sync 3, %0;"   :: "n"(NE)       : "memory")

// One 20-MAC tap slice at an immediate-offset address
#define TAP_ACC(W, ptr)                                                   \
    do {                                                                  \
        const ulonglong2* hv = reinterpret_cast<const ulonglong2*>(ptr);  \
        ulonglong2 h01 = hv[0];                                           \
        ulonglong2 h23 = hv[1];                                           \
        ulonglong2 h45 = hv[2];                                           \
        ulonglong2 h67 = hv[3];                                           \
        ulonglong2 h89 = hv[4];                                           \
        a0 = ffma2(h01.x, (W)[0], a0);                                    \
        a1 = ffma2(h01.y, (W)[1], a1);                                    \
        a2 = ffma2(h23.x, (W)[2], a2);                                    \
        a3 = ffma2(h23.y, (W)[3], a3);                                    \
        a0 = ffma2(h45.x, (W)[4], a0);                                    \
        a1 = ffma2(h45.y, (W)[5], a1);                                    \
        a2 = ffma2(h67.x, (W)[6], a2);                                    \
        a3 = ffma2(h67.y, (W)[7], a3);                                    \
        a0 = ffma2(h89.x, (W)[8], a0);                                    \
        a1 = ffma2(h89.y, (W)[9], a1);                                    \
    } while (0)

__global__ __launch_bounds__(NTHREADS, 1)
void reservoir_kernel(const float* __restrict__ x,
                      const float* __restrict__ Win,
                      const float* __restrict__ Wfb,
                      const float* __restrict__ bias,
                      float* __restrict__ out)
{
    extern __shared__ float sm[];
    float* Hring = sm;                      // [NSLOT][RDIM] = 21120 f
    float* xs    = Hring + NSLOT * RDIM;    // [SEQ]         = 8192 f
    float* part  = xs + SEQ;                // [4][320]  part[buf][i*4+jh]

    const int b   = blockIdx.x;
    const int tid = threadIdx.x;

    for (int idx = tid; idx < NSLOT * RDIM; idx += NTHREADS) Hring[idx] = 0.0f;
    for (int idx = tid; idx < 4 * NX; idx += NTHREADS) part[idx] = 0.0f;
    const float* xb = x + (size_t)b * SEQ;
    for (int idx = tid; idx < SEQ; idx += NTHREADS) xs[idx] = xb[idx];

    float* outb = out + (size_t)b * SEQ * RDIM;

    __syncthreads();

    if (tid < NX) {
        // ========== PRODUCERS (warps 0-9): old-tap partials for t+3 ==========
        const int xi  = tid % RDIM;          // neuron
        const int xjh = tid / RDIM;          // j-quarter

        // W[0..9]=tau4, W[10..19]=tau24, W[20..29]=tau96, W[30..39]=tau168
        u64 W[40];
#pragma unroll
        for (int k = 0; k < 4; k++) {
            const float* wrow =
                Wfb + ((size_t)(k + 1) * RDIM + xi) * RDIM + xjh * 20;
#pragma unroll
            for (int p = 0; p < 10; p++) {
                unsigned lo = __float_as_uint(wrow[2 * p]);
                unsigned hi = __float_as_uint(wrow[2 * p + 1]);
                W[k * 10 + p] = ((u64)hi << 32) | (u64)lo;
            }
        }

#pragma unroll 1
        for (int T = 0; T < SEQ; T += CHUNK) {
            // partials(t+3) read h[t-1], h[t-21], h[t-93], h[t-165]
            const float* p4b   = Hring + ((unsigned)(T - 1)   & 255u) * RDIM + xjh * 20;
            const float* p24b  = Hring + ((unsigned)(T - 21)  & 255u) * RDIM + xjh * 20;
            const float* p96b  = Hring + ((unsigned)(T - 93)  & 255u) * RDIM + xjh * 20;
            const float* p168b = Hring + ((unsigned)(T - 165) & 255u) * RDIM + xjh * 20;

#pragma unroll
            for (int s = 0; s < CHUNK; ++s) {
                BAR_SYNC_A();                 // h[t-1] published (t = T+s)

                u64 a0 = 0ull, a1 = 0ull, a2 = 0ull, a3 = 0ull;
                TAP_ACC(W +  0, p4b   + s * RDIM);
                TAP_ACC(W + 10, p24b  + s * RDIM);
                TAP_ACC(W + 20, p96b  + s * RDIM);
                TAP_ACC(W + 30, p168b + s * RDIM);
                float2 r = unpack2(fadd2(fadd2(a0, a1), fadd2(a2, a3)));
                part[((s + 3) & 3) * NX + xi * 4 + xjh] = r.x + r.y;

                BAR_ARRIVE_B();               // publish partials(t+3)
            }
        }
    } else {
        // ========== EPILOGUE (warps 10-14): tau=1 + update, 160 threads =====
        const int et = tid - NX;              // 0..159
        const int i  = et >> 1;               // neuron 0..79
        const int hy = et & 1;                // j-half

        u64 W1[20];                           // tau=1 half-row (40 floats)
        {
            const float* wr = Wfb + (size_t)i * RDIM + hy * 40;
#pragma unroll
            for (int p = 0; p < 20; p++) {
                unsigned lo = __float_as_uint(wr[2 * p]);
                unsigned hi = __float_as_uint(wr[2 * p + 1]);
                W1[p] = ((u64)hi << 32) | (u64)lo;
            }
        }
        const float win_i  = Win[i];
        const float bias_i = bias[i];
        float h_i = 0.0f;

        BAR_ARRIVE_A();                       // priming: h[-1] = 0 valid

#pragma unroll 1
        for (int T = 0; T < SEQ; T += CHUNK) {
            const float* hYb   = Hring + ((unsigned)(T - 1) & 255u) * RDIM + hy * 40;
            const int   W0     = T & 255;
            float*      hw     = Hring + W0 * RDIM + i;
            const bool  mirror = (W0 == 0);
            float*      op     = outb + (size_t)T * RDIM + i;
            const float* xp    = xs + T;

#pragma unroll
            for (int s = 0; s < CHUNK; ++s) {
                float xw = fmaf(xp[s], win_i, bias_i);

                BAR_SYNC_E();                 // h[t-1] visible in this group

                // tau=1 half matvec vs h[t-1] (broadcast LDS.128)
                u64 a0 = 0ull, a1 = 0ull, a2 = 0ull, a3 = 0ull;
                {
                    const ulonglong2* hv =
                        reinterpret_cast<const ulonglong2*>(hYb + s * RDIM);
#pragma unroll
                    for (int p = 0; p < 5; p++) {
                        ulonglong2 A = hv[2 * p];
                        ulonglong2 B = hv[2 * p + 1];
                        a0 = ffma2(A.x, W1[4 * p + 0], a0);
                        a1 = ffma2(A.y, W1[4 * p + 1], a1);
                        a2 = ffma2(B.x, W1[4 * p + 2], a2);
                        a3 = ffma2(B.y, W1[4 * p + 3], a3);
                    }
                }
                float2 rr = unpack2(fadd2(fadd2(a0, a1), fadd2(a2, a3)));
                float fh = rr.x + rr.y;
                fh += __shfl_xor_sync(0xffffffffu, fh, 1);   // join halves

                BAR_SYNC_B();                 // partials(t) published

                float4 P = *reinterpret_cast<const float4*>(
                    part + (s & 3) * NX + 4 * i);
                float val = fh + ((P.x + P.y) + (P.z + P.w)) + xw;
                h_i = 0.7f * h_i + 0.3f * fast_tanh(val);

                if (hy == 0) {
                    hw[s * RDIM] = h_i;                     // slot W0+s
                    if (mirror) hw[(256 + s) * RDIM] = h_i; // mirrors 256..263
                } else {
                    op[(size_t)s * RDIM] = h_i;             // gmem stream
                }

                BAR_ARRIVE_A();               // publish h[t] to producers
            }
        }
    }
}

extern "C" void kernel_launch(void* const* d_in, const int* in_sizes, int n_in,
                              void* d_out, int out_size)
{
    const float* x    = (const float*)d_in[0];  // [64, 8192, 1]
    const float* Win  = (const float*)d_in[1];  // [80, 1]
    const float* Wfb  = (const float*)d_in[2];  // [5, 80, 80]
    const float* bias = (const float*)d_in[3];  // [80]
    float* out = (float*)d_out;                 // [64, 8192, 80]

    const int smem_bytes = (NSLOT * RDIM + SEQ + 4 * NX) * sizeof(float);
    cudaFuncSetAttribute(reservoir_kernel,
                         cudaFuncAttributeMaxDynamicSharedMemorySize, smem_bytes);

    reservoir_kernel<<<BATCH, NTHREADS, smem_bytes>>>(x, Win, Wfb, bias, out);
}